// round 15
// baseline (speedup 1.0000x reference)
#include <cuda_runtime.h>
#include <math.h>

typedef unsigned long long ull;

// ---------------------------------------------------------------------------
// QPNF RK45 on GB300 — persistent kernel, warp-PAIR specialized.
// 16 warps/CTA (4/SMSP), 8 pairs x 8 samples. Even warp: W2-GEMV side.
// Odd warp: S-GEMV side. Weight smem traffic same as 8-warp version.
// ---------------------------------------------------------------------------

#define NN    8192
#define BLK   512
#define GRID  128
#define NPAIR 8

#define OFF_W1P   0        // [32 j][128]  = W1[32q+lp][j]  (col 4*lp+q)
#define OFF_W2P   4096     // [128 a][128] = W2[32q+lp][a]
#define OFF_SP    20480    // [128 a][128] = S[a][32q+lp]
#define OFF_B1    36864    // [128] permuted
#define OFF_B2    36992    // [128] permuted
#define OFF_B3IP  37120    // [32]
#define OFF_TRP   37152    // [1] (+3 pad)
#define OFF_PT    37156    // [32 k][32 j] = P[j][k]
#define WTOT      38180
// per-PAIR staging (floats): xIf 256 | hmI 2048 | kdl 64 | y132 16 | err 2x dbl
#define PPW       2400
#define SMEM_BYTES ((WTOT + NPAIR*PPW)*4)   // 229,520 B

__device__ __align__(16) float gW[WTOT];
__device__ __align__(16) float gMT[4096];   // gMT[k*128+b] = M[b][k]
__device__ __align__(16) float gIP[1024];   // IP[j*32+k]
__device__ __align__(16) float gT[4096];    // T[j*128+b]
__device__ __align__(16) float gYbuf[2][NN*33];
__device__ double gErr;
__device__ float  g_t, g_dt, g_dtc, g_t1;
__device__ int    g_done, g_cur;
__device__ unsigned int gCtr;
__device__ unsigned int gGen;

__constant__ float c_A[7][5] = {
  {0,0,0,0,0},
  {0.2f,0,0,0,0},
  {(float)(3.0/40.0),(float)(9.0/40.0),0,0,0},
  {(float)(44.0/45.0),(float)(-56.0/15.0),(float)(32.0/9.0),0,0},
  {(float)(19372.0/6561.0),(float)(-25360.0/2187.0),(float)(64448.0/6561.0),(float)(-212.0/729.0),0},
  {(float)(9017.0/3168.0),(float)(-355.0/33.0),(float)(46732.0/5247.0),(float)(49.0/176.0),(float)(-5103.0/18656.0)},
  {0,0,0,0,0}
};

#define CB1 ((float)(35.0/384.0))
#define CB3 ((float)(500.0/1113.0))
#define CB4 ((float)(125.0/192.0))
#define CB5 ((float)(-2187.0/6784.0))
#define CB6 ((float)(11.0/84.0))
#define CE1 ((float)(35.0/384.0 - 5179.0/57600.0))
#define CE3 ((float)(500.0/1113.0 - 7571.0/16695.0))
#define CE4 ((float)(125.0/192.0 - 393.0/640.0))
#define CE5 ((float)(-2187.0/6784.0 + 92097.0/339200.0))
#define CE6 ((float)(11.0/84.0 - 187.0/2100.0))
#define CE7 ((float)(-1.0/40.0))

#define PACKF(d,x,y)   asm("mov.b64 %0, {%1, %2};" : "=l"(d) : "f"(x), "f"(y))
#define PACKD(d,x)     asm("mov.b64 %0, {%1, %1};" : "=l"(d) : "f"(x))
#define UNPACKF(x,y,d) asm("mov.b64 {%0, %1}, %2;" : "=f"(x), "=f"(y) : "l"(d))
#define FMA2(d,a,b)    asm("fma.rn.f32x2 %0, %1, %2, %0;" : "+l"(d) : "l"(a), "l"(b))
#define ADD2(d,a,b)    asm("add.rn.f32x2 %0, %1, %2;" : "=l"(d) : "l"(a), "l"(b))

// ---------------------------------------------------------------------------
__global__ void precompute_a_kernel(const float* __restrict__ G,
                                    const float* __restrict__ W1,
                                    const float* __restrict__ W3,
                                    const float* __restrict__ b1,
                                    const float* __restrict__ b2,
                                    const float* __restrict__ b3,
                                    const float* __restrict__ T)
{
    __shared__ double sA[8][8];
    __shared__ double sX[8][32];
    __shared__ float  sIP[32][32];
    __shared__ float  sPd[32];
    int tid = threadIdx.x;

    if (tid < 64) {
        int i = tid >> 3, j = tid & 7;
        double a = 0;
        for (int k = 0; k < 32; k++) a += (double)G[i*32+k] * (double)G[j*32+k];
        sA[i][j] = a;
    }
    __syncthreads();

    if (tid == 0) {
        double M[8][40];
        for (int i = 0; i < 8; i++) {
            for (int j = 0; j < 8; j++)  M[i][j]   = sA[i][j];
            for (int c = 0; c < 32; c++) M[i][8+c] = (double)G[i*32+c];
        }
        for (int col = 0; col < 8; col++) {
            int p = col; double best = fabs(M[col][col]);
            for (int r = col+1; r < 8; r++) { double v = fabs(M[r][col]); if (v > best) { best = v; p = r; } }
            if (p != col) for (int c = 0; c < 40; c++) { double t = M[col][c]; M[col][c] = M[p][c]; M[p][c] = t; }
            double piv = M[col][col];
            for (int r = 0; r < 8; r++) {
                if (r == col) continue;
                double f = M[r][col] / piv;
                for (int c = col; c < 40; c++) M[r][c] -= f * M[col][c];
            }
        }
        for (int i = 0; i < 8; i++) {
            double d = M[i][i];
            for (int c = 0; c < 32; c++) sX[i][c] = M[i][8+c] / d;
        }
    }
    __syncthreads();

    for (int idx = tid; idx < 1024; idx += 128) {
        int j = idx >> 5, k = idx & 31;
        double pv = 0;
        for (int i = 0; i < 8; i++) pv += (double)G[i*32+j] * sX[i][k];
        gW[OFF_PT + k*32 + j] = (float)pv;
        float ip = (float)(((j == k) ? 1.0 : 0.0) - pv);
        sIP[j][k] = ip;
        gIP[j*32 + k] = ip;
        if (j == k) sPd[j] = (float)pv;
    }
    __syncthreads();

    if (tid == 0) {
        float tr = 0.f;
        for (int j = 0; j < 32; j++) tr += sPd[j];
        gW[OFF_TRP] = tr;
        gW[OFF_TRP+1] = 0.f; gW[OFF_TRP+2] = 0.f; gW[OFF_TRP+3] = 0.f;
    }

    if (tid < 32) {
        int k = tid; float v = 0.f;
        for (int j = 0; j < 32; j++) v += b3[j] * sIP[j][k];
        gW[OFF_B3IP + k] = v;
    }
    for (int idx = tid; idx < 4096; idx += 128) {
        int j = idx >> 7, b = idx & 127;
        float v = 0.f;
        for (int k = 0; k < 32; k++) v += sIP[j][k] * W3[k*128+b];
        gT[idx] = v;
    }
    for (int idx = tid; idx < 4096; idx += 128) {
        int j = idx >> 7, c = idx & 127;
        int q = c & 3, lp = c >> 2;
        gW[OFF_W1P + idx] = W1[(32*q+lp)*32 + j];
    }
    if (tid < 128) {
        int q = tid & 3, lp = tid >> 2;
        gW[OFF_B1 + tid] = b1[32*q+lp];
        gW[OFF_B2 + tid] = b2[32*q+lp];
    }

    if (tid == 0) {
        float t1 = 2.0f * T[0];
        g_t1 = t1; g_t = 0.f; g_dt = 0.25f;
        int done = (0.f >= t1 - 1e-9f);
        g_done = done;
        g_dtc = done ? 1e-3f : fminf(0.25f, t1);
        g_cur = 0;
        gErr = 0.0;
        gCtr = 0u;
        gGen = 0u;
    }
}

__global__ void precompute_b_kernel(const float* __restrict__ W1,
                                    const float* __restrict__ W2,
                                    const float* __restrict__ W3)
{
    int idx = blockIdx.x*256 + threadIdx.x;
    if (idx < 16384) {
        int a = idx >> 7, c = idx & 127;
        int q = c & 3, lp = c >> 2;
        int b = 32*q + lp;
        float e = 0.f;
        for (int j = 0; j < 32; j++) e += W1[a*32+j] * gT[j*128+b];
        gW[OFF_SP + idx] = e * W2[b*128+a];
    } else if (idx < 32768) {
        int i = idx - 16384;
        int a = i >> 7, c = i & 127;
        int q = c & 3, lp = c >> 2;
        gW[OFF_W2P + i] = W2[(32*q+lp)*128 + a];
    } else if (idx < 36864) {
        int i = idx - 32768;
        int k = i >> 7, b = i & 127;
        float m = 0.f;
        for (int j = 0; j < 32; j++) m += W3[j*128+b] * gIP[j*32+k];
        gMT[i] = m;
    }
}

__global__ void init_y_kernel(const float* __restrict__ z)
{
    int stride = gridDim.x * blockDim.x;
    for (int idx = blockIdx.x*blockDim.x + threadIdx.x; idx < NN*33; idx += stride) {
        int n = idx / 33, c = idx - n*33;
        gYbuf[0][idx] = (c < 32) ? z[n*32 + c] : 0.f;
    }
}

// ---------------------------------------------------------------------------
// Persistent warp-pair kernel.
// ---------------------------------------------------------------------------
__global__ void __launch_bounds__(BLK, 1) steps_kernel()
{
    extern __shared__ float sm[];
    __shared__ int   s_cur;
    __shared__ float s_dtc;

    {   // stage weights ONCE
        float4* dst = (float4*)sm;
        const float4* src = (const float4*)gW;
        for (int i = threadIdx.x; i < WTOT/4; i += BLK) dst[i] = src[i];
    }

    const float* sW1P  = sm + OFF_W1P;
    const float* sW2P  = sm + OFF_W2P;
    const float* sSP   = sm + OFF_SP;
    const float* sB1   = sm + OFF_B1;
    const float* sB2   = sm + OFF_B2;
    const float* sB3IP = sm + OFF_B3IP;

    const int warp = threadIdx.x >> 5, lane = threadIdx.x & 31;
    const int wp   = warp & 1;          // 0 = A (W side), 1 = B (S side)
    const int pair = warp >> 1;
    const int barid = 1 + pair;

    float* ws   = sm + WTOT + pair*PPW;
    float* xIf  = ws;            // [sp][2lane] (256 fl); reused as dz-exchange
    float* hmI  = ws + 256;      // [sp][4a] {h_lo,h_hi,m_lo,m_hi} (2048 fl)
    float* kdl  = ws + 2304;     // dlp per stage [m*8+s] (56 fl of 64)
    float* y132s= ws + 2368;     // y1 col-32 (8 fl)
    // err: 2 doubles at ws+2384 (+2*wp)

    #define BARP() asm volatile("bar.sync %0, 64;" :: "r"(barid) : "memory")

    const int n0 = blockIdx.x*64 + pair*8;   // pair's first sample
    const int sb = wp*4;                      // this warp's sample offset

    __syncthreads();
    const float trP = sm[OFF_TRP];

    #pragma unroll 1
    for (int step = 0; step < 10; step++) {
        if (threadIdx.x == 0) {
            s_cur = *(volatile int*)&g_cur;
            s_dtc = *(volatile float*)&g_dtc;
        }
        __syncthreads();
        const int   cur = s_cur;
        const float dtc = s_dtc;
        const float* __restrict__ Y  = gYbuf[cur];
        float* __restrict__       Y1 = gYbuf[cur ^ 1];

        float yr[4], y1r[4];
        #pragma unroll
        for (int s = 0; s < 4; s++) { yr[s] = Y[(n0+sb+s)*33 + lane]; y1r[s] = 0.f; }
        float y32[8];
        if (wp == 1 && lane == 0) {
            #pragma unroll
            for (int s = 0; s < 8; s++) y32[s] = Y[(n0+s)*33 + 32];
        }

        float k0[4],k1[4],k2[4],k3[4],k4[4],k5[4];
        #pragma unroll
        for (int s = 0; s < 4; s++) { k0[s]=0;k1[s]=0;k2[s]=0;k3[s]=0;k4[s]=0;k5[s]=0; }
        float lsum = 0.f;
        float dlp[8];

        #pragma unroll 1
        for (int m = 0; m < 7; m++) {
            const float a0=c_A[m][0], a1=c_A[m][1], a2=c_A[m][2], a3=c_A[m][3], a4=c_A[m][4];

            BARP();   // prev-stage xIf readers done
            // ---- S0: x formation for OWN 4 samples ----
            {
                float xv[4];
                #pragma unroll
                for (int s = 0; s < 4; s++) {
                    float base = (m == 6) ? y1r[s] : yr[s];
                    float acc = a0*k0[s] + a1*k1[s] + a2*k2[s] + a3*k3[s] + a4*k4[s];
                    xv[s] = fmaf(dtc, acc, base);
                }
                ull xpa, xpb;
                PACKF(xpa, xv[0], xv[1]); PACKF(xpb, xv[2], xv[3]);
                *(ull*)(xIf + (2*wp  )*64 + 2*lane) = xpa;
                *(ull*)(xIf + (2*wp+1)*64 + 2*lane) = xpb;
            }
            BARP();   // x visible

            // ---- layer 1: this warp's two q outputs, all 8 samples ----
            {
                ull L[2][4];
                #pragma unroll
                for (int qi = 0; qi < 2; qi++)
                    #pragma unroll
                    for (int sp = 0; sp < 4; sp++) L[qi][sp] = 0ull;
                #pragma unroll 4
                for (int j = 0; j < 32; j++) {
                    ull wp2 = *(const ull*)(sW1P + j*128 + 4*lane + 2*wp);
                    float w0, w1; UNPACKF(w0, w1, wp2);
                    ull x0 = *(const ull*)(xIf + 0*64 + 2*j);
                    ull x1 = *(const ull*)(xIf + 1*64 + 2*j);
                    ull x2 = *(const ull*)(xIf + 2*64 + 2*j);
                    ull x3 = *(const ull*)(xIf + 3*64 + 2*j);
                    { ull t; PACKD(t, w0); FMA2(L[0][0],t,x0); FMA2(L[0][1],t,x1); FMA2(L[0][2],t,x2); FMA2(L[0][3],t,x3); }
                    { ull t; PACKD(t, w1); FMA2(L[1][0],t,x0); FMA2(L[1][1],t,x1); FMA2(L[1][2],t,x2); FMA2(L[1][3],t,x3); }
                }
                #pragma unroll
                for (int qi = 0; qi < 2; qi++) {
                    int qa = 2*wp + qi;
                    float bb = sB1[4*lane + qa];
                    int a = lane + 32*qa;
                    #pragma unroll
                    for (int sp = 0; sp < 4; sp++) {
                        float lo, hi; UNPACKF(lo, hi, L[qi][sp]);
                        lo += bb; hi += bb;
                        float4 hm;
                        hm.x = fmaxf(lo, 0.f); hm.y = fmaxf(hi, 0.f);
                        hm.z = (lo > 0.f) ? 1.f : 0.f;
                        hm.w = (hi > 0.f) ? 1.f : 0.f;
                        *(float4*)(hmI + sp*512 + 4*a) = hm;
                    }
                }
            }
            BARP();   // h1/m visible

            // ---- layer 2: A = W2-GEMV (h), B = S-GEMV (m) ----
            ull ACC[4][4];
            #pragma unroll
            for (int q = 0; q < 4; q++)
                #pragma unroll
                for (int sp = 0; sp < 4; sp++) ACC[q][sp] = 0ull;
            {
                const float* wbase = (wp == 0) ? sW2P : sSP;
                const int    hoff  = (wp == 0) ? 0 : 2;     // h slot vs m slot
                #pragma unroll 4
                for (int a = 0; a < 128; a++) {
                    const float4 w = *(const float4*)(wbase + a*128 + 4*lane);
                    ull g0 = *(const ull*)(hmI + 0*512 + 4*a + hoff);
                    ull g1 = *(const ull*)(hmI + 1*512 + 4*a + hoff);
                    ull g2 = *(const ull*)(hmI + 2*512 + 4*a + hoff);
                    ull g3 = *(const ull*)(hmI + 3*512 + 4*a + hoff);
                    { ull t; PACKD(t, w.x); FMA2(ACC[0][0],t,g0); FMA2(ACC[0][1],t,g1); FMA2(ACC[0][2],t,g2); FMA2(ACC[0][3],t,g3); }
                    { ull t; PACKD(t, w.y); FMA2(ACC[1][0],t,g0); FMA2(ACC[1][1],t,g1); FMA2(ACC[1][2],t,g2); FMA2(ACC[1][3],t,g3); }
                    { ull t; PACKD(t, w.z); FMA2(ACC[2][0],t,g0); FMA2(ACC[2][1],t,g1); FMA2(ACC[2][2],t,g2); FMA2(ACC[2][3],t,g3); }
                    { ull t; PACKD(t, w.w); FMA2(ACC[3][0],t,g0); FMA2(ACC[3][1],t,g1); FMA2(ACC[3][2],t,g2); FMA2(ACC[3][3],t,g3); }
                }
            }

            // ---- A: h2 = relu(pre2+b2) -> h slots (B only reads m slots now) ----
            if (wp == 0) {
                const float4 bv = *(const float4*)(sB2 + 4*lane);
                const float bb[4] = {bv.x, bv.y, bv.z, bv.w};
                #pragma unroll
                for (int q = 0; q < 4; q++) {
                    int a = lane + 32*q;
                    #pragma unroll
                    for (int sp = 0; sp < 4; sp++) {
                        float lo, hi; UNPACKF(lo, hi, ACC[q][sp]);
                        lo += bb[q]; hi += bb[q];
                        ull hp; PACKF(hp, fmaxf(lo,0.f), fmaxf(hi,0.f));
                        *(ull*)(hmI + sp*512 + 4*a) = hp;
                    }
                }
            }
            BARP();   // h2 visible; S-GEMV done

            // ---- dz partials + dlp ----
            ull D[4];
            if (wp == 0) {
                // A: M-GEMV lower half (b = 0..63)
                D[0]=0ull; D[1]=0ull; D[2]=0ull; D[3]=0ull;
                const float4* gMT4 = (const float4*)(gMT) + lane*32;
                #pragma unroll 4
                for (int b4 = 0; b4 < 16; b4++) {
                    const float4 mv = gMT4[b4];
                    int b = 4*b4;
                    { ull t; PACKD(t, mv.x); FMA2(D[0],t,*(const ull*)(hmI+0*512+4*b));    FMA2(D[1],t,*(const ull*)(hmI+1*512+4*b));    FMA2(D[2],t,*(const ull*)(hmI+2*512+4*b));    FMA2(D[3],t,*(const ull*)(hmI+3*512+4*b)); }
                    { ull t; PACKD(t, mv.y); FMA2(D[0],t,*(const ull*)(hmI+0*512+4*b+4));  FMA2(D[1],t,*(const ull*)(hmI+1*512+4*b+4));  FMA2(D[2],t,*(const ull*)(hmI+2*512+4*b+4));  FMA2(D[3],t,*(const ull*)(hmI+3*512+4*b+4)); }
                    { ull t; PACKD(t, mv.z); FMA2(D[0],t,*(const ull*)(hmI+0*512+4*b+8));  FMA2(D[1],t,*(const ull*)(hmI+1*512+4*b+8));  FMA2(D[2],t,*(const ull*)(hmI+2*512+4*b+8));  FMA2(D[3],t,*(const ull*)(hmI+3*512+4*b+8)); }
                    { ull t; PACKD(t, mv.w); FMA2(D[0],t,*(const ull*)(hmI+0*512+4*b+12)); FMA2(D[1],t,*(const ull*)(hmI+1*512+4*b+12)); FMA2(D[2],t,*(const ull*)(hmI+2*512+4*b+12)); FMA2(D[3],t,*(const ull*)(hmI+3*512+4*b+12)); }
                }
            } else {
                // B: dlp gating + reduction
                #pragma unroll
                for (int s = 0; s < 8; s++) dlp[s] = 0.f;
                #pragma unroll
                for (int q = 0; q < 4; q++) {
                    int a = lane + 32*q;
                    #pragma unroll
                    for (int sp = 0; sp < 4; sp++) {
                        ull h2p = *(const ull*)(hmI + sp*512 + 4*a);
                        float lo, hi; UNPACKF(lo, hi, h2p);
                        float rl, rh; UNPACKF(rl, rh, ACC[q][sp]);
                        if (lo > 0.f) dlp[2*sp]   += rl;
                        if (hi > 0.f) dlp[2*sp+1] += rh;
                    }
                }
                #pragma unroll
                for (int s = 0; s < 8; s++) {
                    float v = dlp[s];
                    v += __shfl_xor_sync(0xffffffffu, v, 16);
                    v += __shfl_xor_sync(0xffffffffu, v, 8);
                    v += __shfl_xor_sync(0xffffffffu, v, 4);
                    v += __shfl_xor_sync(0xffffffffu, v, 2);
                    v += __shfl_xor_sync(0xffffffffu, v, 1);
                    dlp[s] = v + trP;
                }
                if (lane == 0) {
                    #pragma unroll
                    for (int s = 0; s < 8; s++) kdl[m*8 + s] = dlp[s];
                }
                // B: b3IP + x·P + M-GEMV upper half (b = 64..127)
                { float bi = sB3IP[lane]; PACKD(D[0], bi); D[1]=D[0]; D[2]=D[0]; D[3]=D[0]; }
                const float4* sPT4 = (const float4*)(sm + OFF_PT) + lane*8;
                #pragma unroll
                for (int j4 = 0; j4 < 8; j4++) {
                    const float4 pv = sPT4[j4];
                    int j = 4*j4;
                    { ull t; PACKD(t, pv.x); FMA2(D[0],t,*(const ull*)(xIf+0*64+2*j));   FMA2(D[1],t,*(const ull*)(xIf+1*64+2*j));   FMA2(D[2],t,*(const ull*)(xIf+2*64+2*j));   FMA2(D[3],t,*(const ull*)(xIf+3*64+2*j)); }
                    { ull t; PACKD(t, pv.y); FMA2(D[0],t,*(const ull*)(xIf+0*64+2*j+2)); FMA2(D[1],t,*(const ull*)(xIf+1*64+2*j+2)); FMA2(D[2],t,*(const ull*)(xIf+2*64+2*j+2)); FMA2(D[3],t,*(const ull*)(xIf+3*64+2*j+2)); }
                    { ull t; PACKD(t, pv.z); FMA2(D[0],t,*(const ull*)(xIf+0*64+2*j+4)); FMA2(D[1],t,*(const ull*)(xIf+1*64+2*j+4)); FMA2(D[2],t,*(const ull*)(xIf+2*64+2*j+4)); FMA2(D[3],t,*(const ull*)(xIf+3*64+2*j+4)); }
                    { ull t; PACKD(t, pv.w); FMA2(D[0],t,*(const ull*)(xIf+0*64+2*j+6)); FMA2(D[1],t,*(const ull*)(xIf+1*64+2*j+6)); FMA2(D[2],t,*(const ull*)(xIf+2*64+2*j+6)); FMA2(D[3],t,*(const ull*)(xIf+3*64+2*j+6)); }
                }
                const float4* gMT4 = (const float4*)(gMT) + lane*32;
                #pragma unroll 4
                for (int b4 = 16; b4 < 32; b4++) {
                    const float4 mv = gMT4[b4];
                    int b = 4*b4;
                    { ull t; PACKD(t, mv.x); FMA2(D[0],t,*(const ull*)(hmI+0*512+4*b));    FMA2(D[1],t,*(const ull*)(hmI+1*512+4*b));    FMA2(D[2],t,*(const ull*)(hmI+2*512+4*b));    FMA2(D[3],t,*(const ull*)(hmI+3*512+4*b)); }
                    { ull t; PACKD(t, mv.y); FMA2(D[0],t,*(const ull*)(hmI+0*512+4*b+4));  FMA2(D[1],t,*(const ull*)(hmI+1*512+4*b+4));  FMA2(D[2],t,*(const ull*)(hmI+2*512+4*b+4));  FMA2(D[3],t,*(const ull*)(hmI+3*512+4*b+4)); }
                    { ull t; PACKD(t, mv.z); FMA2(D[0],t,*(const ull*)(hmI+0*512+4*b+8));  FMA2(D[1],t,*(const ull*)(hmI+1*512+4*b+8));  FMA2(D[2],t,*(const ull*)(hmI+2*512+4*b+8));  FMA2(D[3],t,*(const ull*)(hmI+3*512+4*b+8)); }
                    { ull t; PACKD(t, mv.w); FMA2(D[0],t,*(const ull*)(hmI+0*512+4*b+12)); FMA2(D[1],t,*(const ull*)(hmI+1*512+4*b+12)); FMA2(D[2],t,*(const ull*)(hmI+2*512+4*b+12)); FMA2(D[3],t,*(const ull*)(hmI+3*512+4*b+12)); }
                }
            }
            BARP();   // xIf reads done (B), M-halves done

            // ---- exchange partials through xIf scratch ----
            if (wp == 0) {
                *(ull*)(xIf +   0 + 2*lane) = D[2];
                *(ull*)(xIf +  64 + 2*lane) = D[3];
            } else {
                *(ull*)(xIf + 128 + 2*lane) = D[0];
                *(ull*)(xIf + 192 + 2*lane) = D[1];
            }
            BARP();

            float kv[4];
            if (wp == 0) {
                ull e0 = *(const ull*)(xIf + 128 + 2*lane);
                ull e1 = *(const ull*)(xIf + 192 + 2*lane);
                ull s0, s1; ADD2(s0, D[0], e0); ADD2(s1, D[1], e1);
                float lo, hi;
                UNPACKF(lo, hi, s0); kv[0] = -lo; kv[1] = -hi;
                UNPACKF(lo, hi, s1); kv[2] = -lo; kv[3] = -hi;
            } else {
                ull e2 = *(const ull*)(xIf +   0 + 2*lane);
                ull e3 = *(const ull*)(xIf +  64 + 2*lane);
                ull s2, s3; ADD2(s2, D[2], e2); ADD2(s3, D[3], e3);
                float lo, hi;
                UNPACKF(lo, hi, s2); kv[0] = -lo; kv[1] = -hi;
                UNPACKF(lo, hi, s3); kv[2] = -lo; kv[3] = -hi;
            }

            if (m == 0) {
                for (int s = 0; s < 4; s++) k0[s] = kv[s];
            } else if (m == 1) {
                for (int s = 0; s < 4; s++) k1[s] = kv[s];
            } else if (m == 2) {
                for (int s = 0; s < 4; s++) k2[s] = kv[s];
            } else if (m == 3) {
                for (int s = 0; s < 4; s++) k3[s] = kv[s];
            } else if (m == 4) {
                for (int s = 0; s < 4; s++) k4[s] = kv[s];
            } else if (m == 5) {
                for (int s = 0; s < 4; s++) k5[s] = kv[s];
            }

            if (m == 5) {
                #pragma unroll
                for (int s = 0; s < 4; s++) {
                    float acc = CB1*k0[s] + CB3*k2[s] + CB4*k3[s] + CB5*k4[s] + CB6*k5[s];
                    y1r[s] = fmaf(dtc, acc, yr[s]);
                    Y1[(n0+sb+s)*33 + lane] = y1r[s];
                }
                if (wp == 1 && lane == 0) {
                    #pragma unroll
                    for (int s = 0; s < 8; s++) {
                        float acc = CB1*kdl[0*8+s] + CB3*kdl[2*8+s] + CB4*kdl[3*8+s]
                                  + CB5*kdl[4*8+s] + CB6*kdl[5*8+s];
                        float v = fmaf(dtc, acc, y32[s]);
                        y132s[s] = v;
                        Y1[(n0+s)*33 + 32] = v;
                    }
                }
            }
            if (m == 6) {
                #pragma unroll
                for (int s = 0; s < 4; s++) {
                    float ev = dtc*(CE1*k0[s] + CE3*k2[s] + CE4*k3[s]
                                  + CE5*k4[s] + CE6*k5[s] + CE7*kv[s]);
                    float tol = 1e-5f + 1e-5f*fmaxf(fabsf(yr[s]), fabsf(y1r[s]));
                    float q = ev / tol;
                    lsum += q*q;
                }
                if (wp == 1 && lane == 0) {
                    #pragma unroll
                    for (int s = 0; s < 8; s++) {
                        float ev = dtc*(CE1*kdl[0*8+s] + CE3*kdl[2*8+s] + CE4*kdl[3*8+s]
                                      + CE5*kdl[4*8+s] + CE6*kdl[5*8+s] + CE7*dlp[s]);
                        float tol = 1e-5f + 1e-5f*fmaxf(fabsf(y32[s]), fabsf(y132s[s]));
                        float q = ev / tol;
                        lsum += q*q;
                    }
                }
            }
        }   // stage loop

        // ---- block error reduction ----
        {
            float v = lsum;
            v += __shfl_xor_sync(0xffffffffu, v, 16);
            v += __shfl_xor_sync(0xffffffffu, v, 8);
            v += __shfl_xor_sync(0xffffffffu, v, 4);
            v += __shfl_xor_sync(0xffffffffu, v, 2);
            v += __shfl_xor_sync(0xffffffffu, v, 1);
            if (lane == 0) *(double*)(ws + 2384 + 2*wp) = (double)v;
        }
        __syncthreads();

        // ---- grid barrier + fused controller in last-arriving block ----
        if (threadIdx.x == 0) {
            double tot = 0.0;
            for (int p = 0; p < NPAIR; p++) {
                const float* pb = sm + WTOT + p*PPW;
                tot += *(const double*)(pb + 2384) + *(const double*)(pb + 2386);
            }
            atomicAdd(&gErr, tot);
            __threadfence();
            unsigned int arrived = atomicAdd(&gCtr, 1u);
            if (arrived == GRID - 1) {
                double sum = atomicAdd(&gErr, 0.0);
                atomicExch((ull*)&gErr, 0ull);
                atomicExch(&gCtr, 0u);
                float errn = sqrtf((float)(sum / (8192.0*33.0)));
                int done = *(volatile int*)&g_done;
                int accept = (!done) && (errn <= 1.0f);
                float t  = *(volatile float*)&g_t;
                float dt = *(volatile float*)&g_dt;
                float t1 = *(volatile float*)&g_t1;
                if (accept) { t += dtc; *(volatile int*)&g_cur = cur ^ 1; }
                float factor = fminf(fmaxf(0.9f * powf(errn, -0.2f), 0.2f), 10.0f);
                float dtn = done ? dt : fminf(fmaxf(dtc*factor, 1e-6f), t1);
                *(volatile float*)&g_t  = t;
                *(volatile float*)&g_dt = dtn;
                int done2 = (t >= t1 - 1e-9f);
                *(volatile int*)&g_done = done2;
                *(volatile float*)&g_dtc = done2 ? 1e-3f : fminf(dtn, t1 - t);
                __threadfence();
                atomicExch(&gGen, (unsigned int)(step + 1));
            }
            while (*((volatile unsigned int*)&gGen) < (unsigned int)(step + 1))
                __nanosleep(64);
        }
        __syncthreads();
    }   // step loop
    #undef BARP
}

// ---------------------------------------------------------------------------
__global__ void writeout_kernel(float* __restrict__ out)
{
    const float* Y = gYbuf[g_cur];
    int stride = gridDim.x * blockDim.x;
    for (int idx = blockIdx.x*blockDim.x + threadIdx.x; idx < NN*32; idx += stride) {
        int n = idx >> 5, j = idx & 31;
        out[idx] = Y[n*33 + j];
    }
}

// ---------------------------------------------------------------------------
extern "C" void kernel_launch(void* const* d_in, const int* in_sizes, int n_in,
                              void* d_out, int out_size)
{
    const float* z   = (const float*)d_in[0];
    const float* G   = (const float*)d_in[1];
    const float* W1  = (const float*)d_in[2];
    const float* b1  = (const float*)d_in[3];
    const float* W2  = (const float*)d_in[4];
    const float* b2  = (const float*)d_in[5];
    const float* W3  = (const float*)d_in[6];
    const float* b3  = (const float*)d_in[7];
    const float* T   = (const float*)d_in[8];

    cudaFuncSetAttribute(steps_kernel, cudaFuncAttributeMaxDynamicSharedMemorySize, SMEM_BYTES);

    precompute_a_kernel<<<1, 128>>>(G, W1, W3, b1, b2, b3, T);
    precompute_b_kernel<<<144, 256>>>(W1, W2, W3);
    init_y_kernel<<<256, 256>>>(z);

    steps_kernel<<<GRID, BLK, SMEM_BYTES>>>();

    writeout_kernel<<<256, 256>>>((float*)d_out);
}

// round 16
// speedup vs baseline: 1.1729x; 1.1729x over previous
#include <cuda_runtime.h>
#include <math.h>

typedef unsigned long long ull;

// ---------------------------------------------------------------------------
// QPNF RK45 on GB300 — ONE persistent kernel, FSAL (k7 -> next k1) reuse.
// 8 warps/CTA, 8 samples/warp, f32x2 packed FMA, grid-wide spin barrier.
// ---------------------------------------------------------------------------

#define NN    8192
#define NWARP 8
#define BLK   256
#define GRID  128

#define OFF_W1P   0        // [32 j][128]  = W1[32q+lp][j]
#define OFF_W2P   4096     // [128 a][128] = W2[32q+lp][a]
#define OFF_SP    20480    // [128 a][128] = S[a][32q+lp]
#define OFF_B1    36864    // [128] permuted
#define OFF_B2    36992    // [128] permuted
#define OFF_B3IP  37120    // [32]
#define OFF_TRP   37152    // [1] (+3 pad)
#define OFF_PT    37156    // [32 k][32 j] = P[j][k]
#define WTOT      38180
// per-warp staging (floats): xI 256 | hmI 2048 | kdl 56 | err(double) @2368
#define PW        2432
#define SMEM_BYTES ((WTOT + NWARP*PW)*4)   // 230,544 B

__device__ __align__(16) float gW[WTOT];
__device__ __align__(16) float gMT[4096];   // gMT[k*128+b] = M[b][k]
__device__ __align__(16) float gIP[1024];   // IP[j*32+k]
__device__ __align__(16) float gT[4096];    // T[j*128+b]
__device__ __align__(16) float gYbuf[2][NN*33];
__device__ double gErr;
__device__ float  g_t, g_dt, g_dtc, g_t1;
__device__ int    g_done, g_cur;
__device__ unsigned int gCtr;
__device__ unsigned int gGen;

__constant__ float c_A[7][5] = {
  {0,0,0,0,0},
  {0.2f,0,0,0,0},
  {(float)(3.0/40.0),(float)(9.0/40.0),0,0,0},
  {(float)(44.0/45.0),(float)(-56.0/15.0),(float)(32.0/9.0),0,0},
  {(float)(19372.0/6561.0),(float)(-25360.0/2187.0),(float)(64448.0/6561.0),(float)(-212.0/729.0),0},
  {(float)(9017.0/3168.0),(float)(-355.0/33.0),(float)(46732.0/5247.0),(float)(49.0/176.0),(float)(-5103.0/18656.0)},
  {0,0,0,0,0}
};

#define CB1 ((float)(35.0/384.0))
#define CB3 ((float)(500.0/1113.0))
#define CB4 ((float)(125.0/192.0))
#define CB5 ((float)(-2187.0/6784.0))
#define CB6 ((float)(11.0/84.0))
#define CE1 ((float)(35.0/384.0 - 5179.0/57600.0))
#define CE3 ((float)(500.0/1113.0 - 7571.0/16695.0))
#define CE4 ((float)(125.0/192.0 - 393.0/640.0))
#define CE5 ((float)(-2187.0/6784.0 + 92097.0/339200.0))
#define CE6 ((float)(11.0/84.0 - 187.0/2100.0))
#define CE7 ((float)(-1.0/40.0))

#define PACKF(d,x,y)   asm("mov.b64 %0, {%1, %2};" : "=l"(d) : "f"(x), "f"(y))
#define PACKD(d,x)     asm("mov.b64 %0, {%1, %1};" : "=l"(d) : "f"(x))
#define UNPACKF(x,y,d) asm("mov.b64 {%0, %1}, %2;" : "=f"(x), "=f"(y) : "l"(d))
#define FMA2(d,a,b)    asm("fma.rn.f32x2 %0, %1, %2, %0;" : "+l"(d) : "l"(a), "l"(b))

// ---------------------------------------------------------------------------
__global__ void precompute_a_kernel(const float* __restrict__ G,
                                    const float* __restrict__ W1,
                                    const float* __restrict__ W3,
                                    const float* __restrict__ b1,
                                    const float* __restrict__ b2,
                                    const float* __restrict__ b3,
                                    const float* __restrict__ T)
{
    __shared__ double sA[8][8];
    __shared__ double sX[8][32];
    __shared__ float  sIP[32][32];
    __shared__ float  sPd[32];
    int tid = threadIdx.x;

    if (tid < 64) {
        int i = tid >> 3, j = tid & 7;
        double a = 0;
        for (int k = 0; k < 32; k++) a += (double)G[i*32+k] * (double)G[j*32+k];
        sA[i][j] = a;
    }
    __syncthreads();

    if (tid == 0) {
        double M[8][40];
        for (int i = 0; i < 8; i++) {
            for (int j = 0; j < 8; j++)  M[i][j]   = sA[i][j];
            for (int c = 0; c < 32; c++) M[i][8+c] = (double)G[i*32+c];
        }
        for (int col = 0; col < 8; col++) {
            int p = col; double best = fabs(M[col][col]);
            for (int r = col+1; r < 8; r++) { double v = fabs(M[r][col]); if (v > best) { best = v; p = r; } }
            if (p != col) for (int c = 0; c < 40; c++) { double t = M[col][c]; M[col][c] = M[p][c]; M[p][c] = t; }
            double piv = M[col][col];
            for (int r = 0; r < 8; r++) {
                if (r == col) continue;
                double f = M[r][col] / piv;
                for (int c = col; c < 40; c++) M[r][c] -= f * M[col][c];
            }
        }
        for (int i = 0; i < 8; i++) {
            double d = M[i][i];
            for (int c = 0; c < 32; c++) sX[i][c] = M[i][8+c] / d;
        }
    }
    __syncthreads();

    for (int idx = tid; idx < 1024; idx += 128) {
        int j = idx >> 5, k = idx & 31;
        double pv = 0;
        for (int i = 0; i < 8; i++) pv += (double)G[i*32+j] * sX[i][k];
        gW[OFF_PT + k*32 + j] = (float)pv;
        float ip = (float)(((j == k) ? 1.0 : 0.0) - pv);
        sIP[j][k] = ip;
        gIP[j*32 + k] = ip;
        if (j == k) sPd[j] = (float)pv;
    }
    __syncthreads();

    if (tid == 0) {
        float tr = 0.f;
        for (int j = 0; j < 32; j++) tr += sPd[j];
        gW[OFF_TRP] = tr;
        gW[OFF_TRP+1] = 0.f; gW[OFF_TRP+2] = 0.f; gW[OFF_TRP+3] = 0.f;
    }

    if (tid < 32) {
        int k = tid; float v = 0.f;
        for (int j = 0; j < 32; j++) v += b3[j] * sIP[j][k];
        gW[OFF_B3IP + k] = v;
    }
    for (int idx = tid; idx < 4096; idx += 128) {
        int j = idx >> 7, b = idx & 127;
        float v = 0.f;
        for (int k = 0; k < 32; k++) v += sIP[j][k] * W3[k*128+b];
        gT[idx] = v;
    }
    for (int idx = tid; idx < 4096; idx += 128) {
        int j = idx >> 7, c = idx & 127;
        int q = c & 3, lp = c >> 2;
        gW[OFF_W1P + idx] = W1[(32*q+lp)*32 + j];
    }
    if (tid < 128) {
        int q = tid & 3, lp = tid >> 2;
        gW[OFF_B1 + tid] = b1[32*q+lp];
        gW[OFF_B2 + tid] = b2[32*q+lp];
    }

    if (tid == 0) {
        float t1 = 2.0f * T[0];
        g_t1 = t1; g_t = 0.f; g_dt = 0.25f;
        int done = (0.f >= t1 - 1e-9f);
        g_done = done;
        g_dtc = done ? 1e-3f : fminf(0.25f, t1);
        g_cur = 0;
        gErr = 0.0;
        gCtr = 0u;
        gGen = 0u;
    }
}

__global__ void precompute_b_kernel(const float* __restrict__ W1,
                                    const float* __restrict__ W2,
                                    const float* __restrict__ W3)
{
    int idx = blockIdx.x*256 + threadIdx.x;
    if (idx < 16384) {
        int a = idx >> 7, c = idx & 127;
        int q = c & 3, lp = c >> 2;
        int b = 32*q + lp;
        float e = 0.f;
        for (int j = 0; j < 32; j++) e += W1[a*32+j] * gT[j*128+b];
        gW[OFF_SP + idx] = e * W2[b*128+a];
    } else if (idx < 32768) {
        int i = idx - 16384;
        int a = i >> 7, c = i & 127;
        int q = c & 3, lp = c >> 2;
        gW[OFF_W2P + i] = W2[(32*q+lp)*128 + a];
    } else if (idx < 36864) {
        int i = idx - 32768;
        int k = i >> 7, b = i & 127;
        float m = 0.f;
        for (int j = 0; j < 32; j++) m += W3[j*128+b] * gIP[j*32+k];
        gMT[i] = m;
    }
}

__global__ void init_y_kernel(const float* __restrict__ z)
{
    int stride = gridDim.x * blockDim.x;
    for (int idx = blockIdx.x*blockDim.x + threadIdx.x; idx < NN*33; idx += stride) {
        int n = idx / 33, c = idx - n*33;
        gYbuf[0][idx] = (c < 32) ? z[n*32 + c] : 0.f;
    }
}

// ---------------------------------------------------------------------------
// Persistent kernel with FSAL: stage 0 skipped for steps >= 1.
// ---------------------------------------------------------------------------
__global__ void __launch_bounds__(BLK, 1) steps_kernel()
{
    extern __shared__ float sm[];
    __shared__ int   s_cur;
    __shared__ float s_dtc;

    {   // stage weights ONCE
        float4* dst = (float4*)sm;
        const float4* src = (const float4*)gW;
        for (int i = threadIdx.x; i < WTOT/4; i += BLK) dst[i] = src[i];
    }

    const float* sW1P  = sm + OFF_W1P;
    const float* sW2P  = sm + OFF_W2P;
    const float* sSP   = sm + OFF_SP;
    const float* sB1   = sm + OFF_B1;
    const float* sB2   = sm + OFF_B2;
    const float* sB3IP = sm + OFF_B3IP;

    const int warp = threadIdx.x >> 5, lane = threadIdx.x & 31;
    float* ws  = sm + WTOT + warp*PW;
    float* xIf = ws;            // [sp][2lane] (256 fl)
    float* hmI = ws + 256;      // [sp][4a] {h_lo,h_hi,m_lo,m_hi} (2048 fl)
    float* kdl = ws + 2304;     // [m*8+s] (56 fl)
    // err slot (double) at ws+2368

    const int n0 = blockIdx.x*64 + warp*8;

    __syncthreads();
    const float trP = sm[OFF_TRP];

    float k0[8],k1[8],k2[8],k3[8],k4[8],k5[8], ksave[8];
    #pragma unroll
    for (int s = 0; s < 8; s++) { k0[s]=0;k1[s]=0;k2[s]=0;k3[s]=0;k4[s]=0;k5[s]=0;ksave[s]=0; }
    int cur_prev = 0;

    #pragma unroll 1
    for (int step = 0; step < 10; step++) {
        if (threadIdx.x == 0) {
            s_cur = *(volatile int*)&g_cur;
            s_dtc = *(volatile float*)&g_dtc;
        }
        __syncthreads();
        const int   cur = s_cur;
        const float dtc = s_dtc;
        const float* __restrict__ Y  = gYbuf[cur];
        float* __restrict__       Y1 = gYbuf[cur ^ 1];

        // FSAL: k1 of this step = k7 of prev step if accepted, else prev k1
        if (step > 0) {
            int accept_prev = (cur != cur_prev);
            if (accept_prev) {
                #pragma unroll
                for (int s = 0; s < 8; s++) k0[s] = ksave[s];
                if (lane == 0) {
                    #pragma unroll
                    for (int s = 0; s < 8; s++) kdl[0*8 + s] = kdl[6*8 + s];
                }
            }
        }
        cur_prev = cur;

        float yr[8], y1r[8], y32[8], y132[8];
        #pragma unroll
        for (int s = 0; s < 8; s++) { yr[s] = Y[(n0+s)*33 + lane]; y1r[s] = 0.f; y32[s] = 0.f; y132[s] = 0.f; }
        if (lane == 0) {
            #pragma unroll
            for (int s = 0; s < 8; s++) y32[s] = Y[(n0+s)*33 + 32];
        }

        float lsum = 0.f;
        float dlp[8];
        const int mstart = (step == 0) ? 0 : 1;

        #pragma unroll 1
        for (int m = mstart; m < 7; m++) {
            const float a0=c_A[m][0], a1=c_A[m][1], a2=c_A[m][2], a3=c_A[m][3], a4=c_A[m][4];

            __syncwarp();
            // ---- form x ----
            {
                float xv[8];
                #pragma unroll
                for (int s = 0; s < 8; s++) {
                    float base = (m == 6) ? y1r[s] : yr[s];
                    float acc = a0*k0[s] + a1*k1[s] + a2*k2[s] + a3*k3[s] + a4*k4[s];
                    xv[s] = fmaf(dtc, acc, base);
                }
                #pragma unroll
                for (int sp = 0; sp < 4; sp++) {
                    ull xp; PACKF(xp, xv[2*sp], xv[2*sp+1]);
                    *(ull*)(xIf + sp*64 + 2*lane) = xp;
                }
            }
            __syncwarp();

            // ---- layer 1 ----
            ull L[4][4];
            #pragma unroll
            for (int q = 0; q < 4; q++)
                #pragma unroll
                for (int sp = 0; sp < 4; sp++) L[q][sp] = 0ull;
            #pragma unroll 4
            for (int j = 0; j < 32; j++) {
                const float4 w = *(const float4*)(sW1P + j*128 + 4*lane);
                ull x0 = *(const ull*)(xIf + 0*64 + 2*j);
                ull x1 = *(const ull*)(xIf + 1*64 + 2*j);
                ull x2 = *(const ull*)(xIf + 2*64 + 2*j);
                ull x3 = *(const ull*)(xIf + 3*64 + 2*j);
                { ull t; PACKD(t, w.x); FMA2(L[0][0],t,x0); FMA2(L[0][1],t,x1); FMA2(L[0][2],t,x2); FMA2(L[0][3],t,x3); }
                { ull t; PACKD(t, w.y); FMA2(L[1][0],t,x0); FMA2(L[1][1],t,x1); FMA2(L[1][2],t,x2); FMA2(L[1][3],t,x3); }
                { ull t; PACKD(t, w.z); FMA2(L[2][0],t,x0); FMA2(L[2][1],t,x1); FMA2(L[2][2],t,x2); FMA2(L[2][3],t,x3); }
                { ull t; PACKD(t, w.w); FMA2(L[3][0],t,x0); FMA2(L[3][1],t,x1); FMA2(L[3][2],t,x2); FMA2(L[3][3],t,x3); }
            }
            // relu + masks
            {
                const float4 bv = *(const float4*)(sB1 + 4*lane);
                const float bb[4] = {bv.x, bv.y, bv.z, bv.w};
                #pragma unroll
                for (int q = 0; q < 4; q++) {
                    int a = lane + 32*q;
                    #pragma unroll
                    for (int sp = 0; sp < 4; sp++) {
                        float lo, hi; UNPACKF(lo, hi, L[q][sp]);
                        lo += bb[q]; hi += bb[q];
                        float4 hm;
                        hm.x = fmaxf(lo, 0.f); hm.y = fmaxf(hi, 0.f);
                        hm.z = (lo > 0.f) ? 1.f : 0.f;
                        hm.w = (hi > 0.f) ? 1.f : 0.f;
                        *(float4*)(hmI + sp*512 + 4*a) = hm;
                    }
                }
            }
            __syncwarp();

            // ---- layer 2 + S-bilinear ----
            ull P[4][4], R[4][4];
            #pragma unroll
            for (int q = 0; q < 4; q++)
                #pragma unroll
                for (int sp = 0; sp < 4; sp++) { P[q][sp]=0ull; R[q][sp]=0ull; }
            #pragma unroll 4
            for (int a = 0; a < 128; a++) {
                const float4 w  = *(const float4*)(sW2P + a*128 + 4*lane);
                const float4 sv = *(const float4*)(sSP  + a*128 + 4*lane);
                const ulonglong2 g0 = *(const ulonglong2*)(hmI + 0*512 + 4*a);
                const ulonglong2 g1 = *(const ulonglong2*)(hmI + 1*512 + 4*a);
                const ulonglong2 g2 = *(const ulonglong2*)(hmI + 2*512 + 4*a);
                const ulonglong2 g3 = *(const ulonglong2*)(hmI + 3*512 + 4*a);
                { ull t; PACKD(t, w.x);  FMA2(P[0][0],t,g0.x); FMA2(P[0][1],t,g1.x); FMA2(P[0][2],t,g2.x); FMA2(P[0][3],t,g3.x); }
                { ull t; PACKD(t, w.y);  FMA2(P[1][0],t,g0.x); FMA2(P[1][1],t,g1.x); FMA2(P[1][2],t,g2.x); FMA2(P[1][3],t,g3.x); }
                { ull t; PACKD(t, w.z);  FMA2(P[2][0],t,g0.x); FMA2(P[2][1],t,g1.x); FMA2(P[2][2],t,g2.x); FMA2(P[2][3],t,g3.x); }
                { ull t; PACKD(t, w.w);  FMA2(P[3][0],t,g0.x); FMA2(P[3][1],t,g1.x); FMA2(P[3][2],t,g2.x); FMA2(P[3][3],t,g3.x); }
                { ull t; PACKD(t, sv.x); FMA2(R[0][0],t,g0.y); FMA2(R[0][1],t,g1.y); FMA2(R[0][2],t,g2.y); FMA2(R[0][3],t,g3.y); }
                { ull t; PACKD(t, sv.y); FMA2(R[1][0],t,g0.y); FMA2(R[1][1],t,g1.y); FMA2(R[1][2],t,g2.y); FMA2(R[1][3],t,g3.y); }
                { ull t; PACKD(t, sv.z); FMA2(R[2][0],t,g0.y); FMA2(R[2][1],t,g1.y); FMA2(R[2][2],t,g2.y); FMA2(R[2][3],t,g3.y); }
                { ull t; PACKD(t, sv.w); FMA2(R[3][0],t,g0.y); FMA2(R[3][1],t,g1.y); FMA2(R[3][2],t,g2.y); FMA2(R[3][3],t,g3.y); }
            }
            __syncwarp();

            // ---- h2 + dlp partials; overwrite hmI h-slots with h2 ----
            #pragma unroll
            for (int s = 0; s < 8; s++) dlp[s] = 0.f;
            {
                const float4 bv = *(const float4*)(sB2 + 4*lane);
                const float bb[4] = {bv.x, bv.y, bv.z, bv.w};
                #pragma unroll
                for (int q = 0; q < 4; q++) {
                    int a = lane + 32*q;
                    #pragma unroll
                    for (int sp = 0; sp < 4; sp++) {
                        float lo, hi; UNPACKF(lo, hi, P[q][sp]);
                        float rl, rh; UNPACKF(rl, rh, R[q][sp]);
                        lo += bb[q]; hi += bb[q];
                        if (lo > 0.f) dlp[2*sp]   += rl;
                        if (hi > 0.f) dlp[2*sp+1] += rh;
                        ull hp; PACKF(hp, fmaxf(lo,0.f), fmaxf(hi,0.f));
                        *(ull*)(hmI + sp*512 + 4*a) = hp;
                    }
                }
            }
            __syncwarp();

            // ---- dlp warp reduction ----
            #pragma unroll
            for (int s = 0; s < 8; s++) {
                float v = dlp[s];
                v += __shfl_xor_sync(0xffffffffu, v, 16);
                v += __shfl_xor_sync(0xffffffffu, v, 8);
                v += __shfl_xor_sync(0xffffffffu, v, 4);
                v += __shfl_xor_sync(0xffffffffu, v, 2);
                v += __shfl_xor_sync(0xffffffffu, v, 1);
                dlp[s] = v + trP;
            }
            if (lane == 0) {
                #pragma unroll
                for (int s = 0; s < 8; s++) kdl[m*8 + s] = dlp[s];
            }

            // ---- dz = -(h2 M + x P + b3IP) ----
            ull D[4];
            { float bi = sB3IP[lane]; PACKD(D[0], bi); D[1]=D[0]; D[2]=D[0]; D[3]=D[0]; }
            {
                const float4* gMT4 = (const float4*)(gMT) + lane*32;
                #pragma unroll 4
                for (int b4 = 0; b4 < 32; b4++) {
                    const float4 mv = gMT4[b4];
                    int b = 4*b4;
                    { ull t; PACKD(t, mv.x); FMA2(D[0],t,*(const ull*)(hmI+0*512+4*b));    FMA2(D[1],t,*(const ull*)(hmI+1*512+4*b));    FMA2(D[2],t,*(const ull*)(hmI+2*512+4*b));    FMA2(D[3],t,*(const ull*)(hmI+3*512+4*b)); }
                    { ull t; PACKD(t, mv.y); FMA2(D[0],t,*(const ull*)(hmI+0*512+4*b+4));  FMA2(D[1],t,*(const ull*)(hmI+1*512+4*b+4));  FMA2(D[2],t,*(const ull*)(hmI+2*512+4*b+4));  FMA2(D[3],t,*(const ull*)(hmI+3*512+4*b+4)); }
                    { ull t; PACKD(t, mv.z); FMA2(D[0],t,*(const ull*)(hmI+0*512+4*b+8));  FMA2(D[1],t,*(const ull*)(hmI+1*512+4*b+8));  FMA2(D[2],t,*(const ull*)(hmI+2*512+4*b+8));  FMA2(D[3],t,*(const ull*)(hmI+3*512+4*b+8)); }
                    { ull t; PACKD(t, mv.w); FMA2(D[0],t,*(const ull*)(hmI+0*512+4*b+12)); FMA2(D[1],t,*(const ull*)(hmI+1*512+4*b+12)); FMA2(D[2],t,*(const ull*)(hmI+2*512+4*b+12)); FMA2(D[3],t,*(const ull*)(hmI+3*512+4*b+12)); }
                }
                const float4* sPT4 = (const float4*)(sm + OFF_PT) + lane*8;
                #pragma unroll
                for (int j4 = 0; j4 < 8; j4++) {
                    const float4 pv = sPT4[j4];
                    int j = 4*j4;
                    { ull t; PACKD(t, pv.x); FMA2(D[0],t,*(const ull*)(xIf+0*64+2*j));   FMA2(D[1],t,*(const ull*)(xIf+1*64+2*j));   FMA2(D[2],t,*(const ull*)(xIf+2*64+2*j));   FMA2(D[3],t,*(const ull*)(xIf+3*64+2*j)); }
                    { ull t; PACKD(t, pv.y); FMA2(D[0],t,*(const ull*)(xIf+0*64+2*j+2)); FMA2(D[1],t,*(const ull*)(xIf+1*64+2*j+2)); FMA2(D[2],t,*(const ull*)(xIf+2*64+2*j+2)); FMA2(D[3],t,*(const ull*)(xIf+3*64+2*j+2)); }
                    { ull t; PACKD(t, pv.z); FMA2(D[0],t,*(const ull*)(xIf+0*64+2*j+4)); FMA2(D[1],t,*(const ull*)(xIf+1*64+2*j+4)); FMA2(D[2],t,*(const ull*)(xIf+2*64+2*j+4)); FMA2(D[3],t,*(const ull*)(xIf+3*64+2*j+4)); }
                    { ull t; PACKD(t, pv.w); FMA2(D[0],t,*(const ull*)(xIf+0*64+2*j+6)); FMA2(D[1],t,*(const ull*)(xIf+1*64+2*j+6)); FMA2(D[2],t,*(const ull*)(xIf+2*64+2*j+6)); FMA2(D[3],t,*(const ull*)(xIf+3*64+2*j+6)); }
                }
            }
            float kv[8];
            #pragma unroll
            for (int sp = 0; sp < 4; sp++) {
                float lo, hi; UNPACKF(lo, hi, D[sp]);
                kv[2*sp] = -lo; kv[2*sp+1] = -hi;
            }

            if (m == 0) {
                for (int s = 0; s < 8; s++) k0[s] = kv[s];
            } else if (m == 1) {
                for (int s = 0; s < 8; s++) k1[s] = kv[s];
            } else if (m == 2) {
                for (int s = 0; s < 8; s++) k2[s] = kv[s];
            } else if (m == 3) {
                for (int s = 0; s < 8; s++) k3[s] = kv[s];
            } else if (m == 4) {
                for (int s = 0; s < 8; s++) k4[s] = kv[s];
            } else if (m == 5) {
                for (int s = 0; s < 8; s++) k5[s] = kv[s];
            } else {
                for (int s = 0; s < 8; s++) ksave[s] = kv[s];   // FSAL save (m==6)
            }

            if (m == 5) {
                #pragma unroll
                for (int s = 0; s < 8; s++) {
                    float acc = CB1*k0[s] + CB3*k2[s] + CB4*k3[s] + CB5*k4[s] + CB6*k5[s];
                    y1r[s] = fmaf(dtc, acc, yr[s]);
                    Y1[(n0+s)*33 + lane] = y1r[s];
                }
                if (lane == 0) {
                    #pragma unroll
                    for (int s = 0; s < 8; s++) {
                        float acc = CB1*kdl[0*8+s] + CB3*kdl[2*8+s] + CB4*kdl[3*8+s]
                                  + CB5*kdl[4*8+s] + CB6*kdl[5*8+s];
                        y132[s] = fmaf(dtc, acc, y32[s]);
                        Y1[(n0+s)*33 + 32] = y132[s];
                    }
                }
            }
            if (m == 6) {
                #pragma unroll
                for (int s = 0; s < 8; s++) {
                    float ev = dtc*(CE1*k0[s] + CE3*k2[s] + CE4*k3[s]
                                  + CE5*k4[s] + CE6*k5[s] + CE7*kv[s]);
                    float tol = 1e-5f + 1e-5f*fmaxf(fabsf(yr[s]), fabsf(y1r[s]));
                    float q = ev / tol;
                    lsum += q*q;
                }
                if (lane == 0) {
                    #pragma unroll
                    for (int s = 0; s < 8; s++) {
                        float ev = dtc*(CE1*kdl[0*8+s] + CE3*kdl[2*8+s] + CE4*kdl[3*8+s]
                                      + CE5*kdl[4*8+s] + CE6*kdl[5*8+s] + CE7*dlp[s]);
                        float tol = 1e-5f + 1e-5f*fmaxf(fabsf(y32[s]), fabsf(y132[s]));
                        float q = ev / tol;
                        lsum += q*q;
                    }
                }
            }
        }   // stage loop

        // ---- block error reduction ----
        {
            float v = lsum;
            v += __shfl_xor_sync(0xffffffffu, v, 16);
            v += __shfl_xor_sync(0xffffffffu, v, 8);
            v += __shfl_xor_sync(0xffffffffu, v, 4);
            v += __shfl_xor_sync(0xffffffffu, v, 2);
            v += __shfl_xor_sync(0xffffffffu, v, 1);
            if (lane == 0) *(double*)(ws + 2368) = (double)v;
        }
        __syncthreads();

        // ---- grid barrier + fused controller in last-arriving block ----
        if (threadIdx.x == 0) {
            double tot = 0.0;
            for (int w = 0; w < NWARP; w++)
                tot += *(const double*)(sm + WTOT + w*PW + 2368);
            atomicAdd(&gErr, tot);
            __threadfence();
            unsigned int arrived = atomicAdd(&gCtr, 1u);
            if (arrived == GRID - 1) {
                double sum = atomicAdd(&gErr, 0.0);
                atomicExch((ull*)&gErr, 0ull);
                atomicExch(&gCtr, 0u);
                float errn = sqrtf((float)(sum / (8192.0*33.0)));
                int done = *(volatile int*)&g_done;
                int accept = (!done) && (errn <= 1.0f);
                float t  = *(volatile float*)&g_t;
                float dt = *(volatile float*)&g_dt;
                float t1 = *(volatile float*)&g_t1;
                if (accept) { t += dtc; *(volatile int*)&g_cur = cur ^ 1; }
                float factor = fminf(fmaxf(0.9f * powf(errn, -0.2f), 0.2f), 10.0f);
                float dtn = done ? dt : fminf(fmaxf(dtc*factor, 1e-6f), t1);
                *(volatile float*)&g_t  = t;
                *(volatile float*)&g_dt = dtn;
                int done2 = (t >= t1 - 1e-9f);
                *(volatile int*)&g_done = done2;
                *(volatile float*)&g_dtc = done2 ? 1e-3f : fminf(dtn, t1 - t);
                __threadfence();
                atomicExch(&gGen, (unsigned int)(step + 1));
            }
            while (*((volatile unsigned int*)&gGen) < (unsigned int)(step + 1))
                __nanosleep(64);
        }
        __syncthreads();
    }   // step loop
}

// ---------------------------------------------------------------------------
__global__ void writeout_kernel(float* __restrict__ out)
{
    const float* Y = gYbuf[g_cur];
    int stride = gridDim.x * blockDim.x;
    for (int idx = blockIdx.x*blockDim.x + threadIdx.x; idx < NN*32; idx += stride) {
        int n = idx >> 5, j = idx & 31;
        out[idx] = Y[n*33 + j];
    }
}

// ---------------------------------------------------------------------------
extern "C" void kernel_launch(void* const* d_in, const int* in_sizes, int n_in,
                              void* d_out, int out_size)
{
    const float* z   = (const float*)d_in[0];
    const float* G   = (const float*)d_in[1];
    const float* W1  = (const float*)d_in[2];
    const float* b1  = (const float*)d_in[3];
    const float* W2  = (const float*)d_in[4];
    const float* b2  = (const float*)d_in[5];
    const float* W3  = (const float*)d_in[6];
    const float* b3  = (const float*)d_in[7];
    const float* T   = (const float*)d_in[8];

    cudaFuncSetAttribute(steps_kernel, cudaFuncAttributeMaxDynamicSharedMemorySize, SMEM_BYTES);

    precompute_a_kernel<<<1, 128>>>(G, W1, W3, b1, b2, b3, T);
    precompute_b_kernel<<<144, 256>>>(W1, W2, W3);
    init_y_kernel<<<256, 256>>>(z);

    steps_kernel<<<GRID, BLK, SMEM_BYTES>>>();

    writeout_kernel<<<256, 256>>>((float*)d_out);
}